// round 9
// baseline (speedup 1.0000x reference)
#include <cuda_runtime.h>
#include <cuda_fp16.h>
#include <cstdint>

#define HH 512
#define WW 512
#define BATCH 32
#define WPR 16                       // uint32 words per row (512 bits)
#define WORDS_PER_IMG (HH * WPR)     // 8192 words = 32KB
#define TILE_H 32
#define GRAY_ROWS (TILE_H + 4)       // 36
#define MAG_ROWS  (TILE_H + 2)       // 34
#define MAGP2 260                    // mag pitch in half2 (2 zero half2 pads each side)
#define HPITCH 17                    // hysteresis exchange pitch (conflict-free)
#define FTHREADS 640

// ---------------- device scratch (no allocations allowed) ----------------
__device__ uint32_t g_weak  [2 * BATCH * WORDS_PER_IMG];
__device__ uint32_t g_strong[2 * BATCH * WORDS_PER_IMG];
__device__ uint32_t g_edges [2 * BATCH * WORDS_PER_IMG];
__device__ unsigned int g_count;
__device__ unsigned int g_done;

__device__ __forceinline__ unsigned spread4(unsigned x) {   // bit i -> bit 4i (8 bits in)
    x &= 0xFFu;
    x = (x | (x << 12)) & 0x000F000Fu;
    x = (x | (x << 6))  & 0x03030303u;
    x = (x | (x << 3))  & 0x11111111u;
    return x;
}

__device__ __forceinline__ __half2 u2h(unsigned u) { return *reinterpret_cast<__half2*>(&u); }
__device__ __forceinline__ unsigned h2u(__half2 h) { return *reinterpret_cast<unsigned*>(&h); }

// pair (X.hi, Y.lo): covers cols (c-1, c) when X = word before Y
__device__ __forceinline__ __half2 prhl(__half2 X, __half2 Y) {
    return __halves2half2(__high2half(X), __low2half(Y));
}

// gray quad: for 4 px (word pair w0=2*c4, w1=2*c4+1), reflect at image edges.
__device__ __forceinline__ void gquad(const __half2* row, int c4,
                                      __half2& L, __half2& C0, __half2& R,
                                      __half2& C1, __half2& R1) {
    uint2 ab = *reinterpret_cast<const uint2*>(&row[2 * c4]);
    __half2 A = u2h(ab.x), B = u2h(ab.y);
    __half2 P = (c4 > 0)   ? row[2 * c4 - 1] : __lowhigh2highlow(A);
    __half2 N = (c4 < 127) ? row[2 * c4 + 2] : __lowhigh2highlow(B);
    L  = (c4 > 0)   ? prhl(P, A) : P;    // reflect: (g1,g0)
    R1 = (c4 < 127) ? prhl(B, N) : N;    // reflect: (g511,g510)
    C0 = A; C1 = B;
    R  = prhl(A, B);
}

// mag quad: zero-padded (2 words each side), branch-free
__device__ __forceinline__ void mquad(const __half2* row, int c4,
                                      __half2& L, __half2& C0, __half2& R,
                                      __half2& C1, __half2& R1) {
    uint2 ab = *reinterpret_cast<const uint2*>(&row[2 * c4 + 2]);
    __half2 A = u2h(ab.x), B = u2h(ab.y);
    __half2 P = row[2 * c4 + 1];
    __half2 N = row[2 * c4 + 4];
    L = prhl(P, A); R = prhl(A, B); R1 = prhl(B, N);
    C0 = A; C1 = B;
}

// Sobel on half2 triples (all values exact integers -> exact in fp16)
__device__ __forceinline__ void sobel2(__half2 tL, __half2 tC, __half2 tR,
                                       __half2 mL, __half2 mR,
                                       __half2 bL, __half2 bC, __half2 bR,
                                       __half2& gx2, __half2& gy2) {
    const __half2 two2 = __floats2half2_rn(2.0f, 2.0f);
    __half2 dt = __hsub2(tR, tL);
    __half2 dm = __hsub2(mR, mL);
    __half2 db = __hsub2(bR, bL);
    gx2 = __hadd2(__hfma2(two2, dm, dt), db);
    __half2 st = __hfma2(two2, tC, __hadd2(tL, tR));
    __half2 sb = __hfma2(two2, bC, __hadd2(bL, bR));
    gy2 = __hsub2(sb, st);
}

__device__ __forceinline__ float grayq(float r, float g, float b) {
    // match XLA: ((0.299*R + 0.587*G) + 0.114*B), each op separately rounded
    float v = __fadd_rn(__fadd_rn(__fmul_rn(0.299f, r), __fmul_rn(0.587f, g)),
                        __fmul_rn(0.114f, b));
    return fminf(fmaxf(floorf(__fmul_rn(v, 255.0f)), 0.0f), 255.0f);
}

// classification for one half2 pair of (gx,gy): 2-bit classes for both px
__device__ __forceinline__ int classify2(__half2 gx2, __half2 gy2) {
    float2 gxf = __half22float2(gx2);
    float2 gyf = __half22float2(gy2);
    float ax0 = fabsf(gxf.x), ay0 = fabsf(gyf.x);
    float ax1 = fabsf(gxf.y), ay1 = fabsf(gyf.y);
    bool h0 = ay0 <= __fmul_rn((float)0.4142135623730951, ax0);
    bool v0 = ay0 >= __fmul_rn((float)2.414213562373095,  ax0);
    bool s0 = __fmul_rn(gxf.x, gyf.x) >= 0.0f;
    bool h1 = ay1 <= __fmul_rn((float)0.4142135623730951, ax1);
    bool v1 = ay1 >= __fmul_rn((float)2.414213562373095,  ax1);
    bool s1 = __fmul_rn(gxf.y, gyf.y) >= 0.0f;
    int cls0 = h0 ? 0 : (v0 ? 1 : (s0 ? 2 : 3));
    int cls1 = h1 ? 0 : (v1 ? 1 : (s1 ? 2 : 3));
    return cls0 | (cls1 << 2);
}

// ---------------- fused gray -> sobel+class -> NMS -> threshold -> bitpack
__global__ __launch_bounds__(FTHREADS, 3) void k_frontend(const float* __restrict__ A,
                                                          const float* __restrict__ B) {
    extern __shared__ __half2 smem2[];
    __half2* sg2 = smem2;                      // [GRAY_ROWS][256]
    __half2* sm2 = smem2 + GRAY_ROWS * 256;    // [MAG_ROWS][MAGP2]
    uint8_t* sdc = (uint8_t*)(smem2 + GRAY_ROWS * 256 + MAG_ROWS * MAGP2); // [TILE_H][128]

    const int tid  = threadIdx.x;
    const int tile = blockIdx.x;
    const int b    = blockIdx.y;
    const int im   = blockIdx.z;
    const int r0   = tile * TILE_H;
    const float* img = (im == 0 ? A : B) + (size_t)b * 3 * HH * WW;

    if (tile == 0 && b == 0 && im == 0 && tid == 0) { g_count = 0u; g_done = 0u; }

    // Stage 1: quantized grayscale, 4 px/thread via float4, reflect rows (halo 2)
    for (int p = tid; p < GRAY_ROWS * 128; p += FTHREADS) {
        int rr = p >> 7, c4 = p & 127;
        int gr = r0 - 2 + rr;
        gr = gr < 0 ? -gr : (gr > HH - 1 ? 2 * (HH - 1) - gr : gr);
        const float4* base = (const float4*)(img + gr * WW) + c4;
        float4 r4 = base[0];
        float4 g4 = base[(HH * WW) / 4];
        float4 b4 = base[(2 * HH * WW) / 4];
        __half2 h01 = __floats2half2_rn(grayq(r4.x, g4.x, b4.x), grayq(r4.y, g4.y, b4.y));
        __half2 h23 = __floats2half2_rn(grayq(r4.z, g4.z, b4.z), grayq(r4.w, g4.w, b4.w));
        uint2 pk; pk.x = h2u(h01); pk.y = h2u(h23);
        *reinterpret_cast<uint2*>(&sg2[rr * 256 + 2 * c4]) = pk;
    }
    __syncthreads();

    // Stage 2: magnitude + direction class, 4 px/thread
    for (int p = tid; p < MAG_ROWS * 128; p += FTHREADS) {
        int rr = p >> 7, c4 = p & 127;
        int gr = r0 - 1 + rr;
        __half2 m20 = __floats2half2_rn(0.0f, 0.0f);
        __half2 m21 = m20;
        if (gr >= 0 && gr < HH) {
            int sr = rr + 1;
            __half2 tL, tC0, tR, tC1, tR1;
            __half2 mL, mC0, mR, mC1, mR1;
            __half2 bL, bC0, bR, bC1, bR1;
            gquad(sg2 + (sr - 1) * 256, c4, tL, tC0, tR, tC1, tR1);
            gquad(sg2 +  sr      * 256, c4, mL, mC0, mR, mC1, mR1);
            gquad(sg2 + (sr + 1) * 256, c4, bL, bC0, bR, bC1, bR1);
            __half2 gx0, gy0, gx1, gy1;
            sobel2(tL, tC0, tR,  mL, mR,  bL, bC0, bR,  gx0, gy0);   // pair0
            sobel2(tR, tC1, tR1, mR, mR1, bR, bC1, bR1, gx1, gy1);   // pair1 (L1=R0)
            m20 = __hadd2(__habs2(gx0), __habs2(gy0));   // <= 2040, exact
            m21 = __hadd2(__habs2(gx1), __habs2(gy1));
            if (rr >= 1 && rr <= TILE_H) {
                int cb = classify2(gx0, gy0) | (classify2(gx1, gy1) << 4);
                sdc[(rr - 1) * 128 + c4] = (uint8_t)cb;
            }
        }
        uint2 pk; pk.x = h2u(m20); pk.y = h2u(m21);
        *reinterpret_cast<uint2*>(&sm2[rr * MAGP2 + 2 * c4 + 2]) = pk;
    }
    {
        uint2 z2; z2.x = 0u; z2.y = 0u;
        for (int r = tid; r < MAG_ROWS; r += FTHREADS) {
            *reinterpret_cast<uint2*>(&sm2[r * MAGP2])       = z2;
            *reinterpret_cast<uint2*>(&sm2[r * MAGP2 + 258]) = z2;
        }
    }
    __syncthreads();

    // Stage 3: NMS from cached mag+class + threshold + bitpack; 4 px/thread
    const int lane = tid & 31;
    const size_t obase = ((size_t)(im * BATCH + b)) * WORDS_PER_IMG;
    const __half2 h25 = __floats2half2_rn(25.0f, 25.0f);
    const __half2 h76 = __floats2half2_rn(76.0f, 76.0f);
    for (int pt = tid; pt < TILE_H * 128; pt += FTHREADS) {
        int rr = pt >> 7, c4 = pt & 127;       // rr uniform per warp

        __half2 tL, tC0, tR, tC1, tR1;
        __half2 mL, mC0, mR, mC1, mR1;
        __half2 bL, bC0, bR, bC1, bR1;
        mquad(sm2 +  rr      * MAGP2, c4, tL, tC0, tR, tC1, tR1);
        mquad(sm2 + (rr + 1) * MAGP2, c4, mL, mC0, mR, mC1, mR1);
        mquad(sm2 + (rr + 2) * MAGP2, c4, bL, bC0, bR, bC1, bR1);

        // pair0 (cols c, c+1)
        unsigned kh0 = __hgt2_mask(mC0, mL)  & __hge2_mask(mC0, mR);
        unsigned kv0 = __hgt2_mask(mC0, tC0) & __hge2_mask(mC0, bC0);
        unsigned k10 = __hgt2_mask(mC0, tL)  & __hge2_mask(mC0, bR);
        unsigned k20 = __hgt2_mask(mC0, tR)  & __hge2_mask(mC0, bL);
        unsigned wm0 = __hgt2_mask(mC0, h25);
        unsigned sm0 = __hgt2_mask(mC0, h76);
        // pair1 (cols c+2, c+3)
        unsigned kh1 = __hgt2_mask(mC1, mR)  & __hge2_mask(mC1, mR1);
        unsigned kv1 = __hgt2_mask(mC1, tC1) & __hge2_mask(mC1, bC1);
        unsigned k11 = __hgt2_mask(mC1, tR)  & __hge2_mask(mC1, bR1);
        unsigned k21 = __hgt2_mask(mC1, tR1) & __hge2_mask(mC1, bR);
        unsigned wm1 = __hgt2_mask(mC1, h25);
        unsigned sm1 = __hgt2_mask(mC1, h76);

        int cb = sdc[rr * 128 + c4];
        int c0 = cb & 3, c1 = (cb >> 2) & 3, c2_ = (cb >> 4) & 3, c3 = (cb >> 6) & 3;
        unsigned s0 = c0 == 0 ? kh0 : (c0 == 1 ? kv0 : (c0 == 2 ? k10 : k20));
        unsigned s1 = c1 == 0 ? kh0 : (c1 == 1 ? kv0 : (c1 == 2 ? k10 : k20));
        unsigned s2 = c2_ == 0 ? kh1 : (c2_ == 1 ? kv1 : (c2_ == 2 ? k11 : k21));
        unsigned s3 = c3 == 0 ? kh1 : (c3 == 1 ? kv1 : (c3 == 2 ? k11 : k21));
        bool wk0 =  (s0 & wm0)         & 1u;
        bool st0 =  (s0 & sm0)         & 1u;
        bool wk1 = ((s1 & wm0) >> 16)  & 1u;
        bool st1 = ((s1 & sm0) >> 16)  & 1u;
        bool wk2 =  (s2 & wm1)         & 1u;
        bool st2 =  (s2 & sm1)         & 1u;
        bool wk3 = ((s3 & wm1) >> 16)  & 1u;
        bool st3 = ((s3 & sm1) >> 16)  & 1u;

        unsigned bw0 = __ballot_sync(0xffffffffu, wk0);
        unsigned bw1 = __ballot_sync(0xffffffffu, wk1);
        unsigned bw2 = __ballot_sync(0xffffffffu, wk2);
        unsigned bw3 = __ballot_sync(0xffffffffu, wk3);
        unsigned bs0 = __ballot_sync(0xffffffffu, st0);
        unsigned bs1 = __ballot_sync(0xffffffffu, st1);
        unsigned bs2 = __ballot_sync(0xffffffffu, st2);
        unsigned bs3 = __ballot_sync(0xffffffffu, st3);

        if (lane < 8) {
            int m = lane & 3;
            bool is_st = lane >= 4;          // lanes 0-3 weak, 4-7 strong
            unsigned x0 = is_st ? bs0 : bw0;
            unsigned x1 = is_st ? bs1 : bw1;
            unsigned x2 = is_st ? bs2 : bw2;
            unsigned x3 = is_st ? bs3 : bw3;
            int sh = 8 * m;
            unsigned wordv = spread4(x0 >> sh) | (spread4(x1 >> sh) << 1)
                           | (spread4(x2 >> sh) << 2) | (spread4(x3 >> sh) << 3);
            uint32_t* dst = is_st ? (g_strong + obase) : (g_weak + obase);
            int wbase = (c4 & ~31) >> 3;           // warp's first word index
            dst[(size_t)(r0 + rr) * WPR + wbase + m] = wordv;
        }
    }
}

// ---------------- bitwise hysteresis: 1 CTA/image, 1 row/thread, regs-resident
__global__ __launch_bounds__(512) void k_hyster() {
    extern __shared__ uint32_t sbuf[];   // 2 buffers of [512][HPITCH]
    const int t = threadIdx.x;           // row index 0..511
    const int im = blockIdx.x >> 5, b = blockIdx.x & 31;
    const size_t base = ((size_t)(im * BATCH + b)) * WORDS_PER_IMG + (size_t)t * WPR;

    uint32_t w[WPR], s[WPR], c[WPR];
    {
        const uint4* pw = (const uint4*)(g_weak + base);
        const uint4* ps = (const uint4*)(g_strong + base);
#pragma unroll
        for (int q = 0; q < 4; q++) {
            uint4 a = pw[q];
            w[4*q+0]=a.x; w[4*q+1]=a.y; w[4*q+2]=a.z; w[4*q+3]=a.w;
            uint4 d = ps[q];
            s[4*q+0]=d.x; s[4*q+1]=d.y; s[4*q+2]=d.z; s[4*q+3]=d.w;
        }
    }
#pragma unroll
    for (int i = 0; i < WPR; i++) c[i] = s[i];

    uint32_t* b0 = sbuf;
    uint32_t* b1 = sbuf + HH * HPITCH;
#pragma unroll
    for (int i = 0; i < WPR; i++) b0[t * HPITCH + i] = c[i];
    __syncthreads();

    for (int it = 0; it < 64; ++it) {
        const uint32_t* rd = (it & 1) ? b1 : b0;
        uint32_t*       wr = (it & 1) ? b0 : b1;
        const uint32_t* pu = rd + (t - 1) * HPITCH;
        const uint32_t* pd = rd + (t + 1) * HPITCH;
        uint32_t vor[WPR];
#pragma unroll
        for (int i = 0; i < WPR; i++) {
            uint32_t u = (t > 0)      ? pu[i] : 0u;
            uint32_t d = (t < HH - 1) ? pd[i] : 0u;
            vor[i] = u | d | c[i];               // vertical max (separable)
        }
        uint32_t ch = 0u;
#pragma unroll
        for (int i = 0; i < WPR; i++) {
            uint32_t lo = (i > 0)       ? vor[i - 1] : 0u;
            uint32_t hi = (i < WPR - 1) ? vor[i + 1] : 0u;
            uint32_t l = __funnelshift_l(lo, vor[i], 1);   // col-1 values
            uint32_t r = __funnelshift_r(vor[i], hi, 1);   // col+1 values
            uint32_t d3 = l | vor[i] | r;                  // 3x3 dilate done
            uint32_t nv = (d3 & w[i]) | s[i];
            ch |= nv ^ c[i];
            c[i] = nv;
            wr[t * HPITCH + i] = nv;
        }
        int any = __syncthreads_or((int)(ch != 0u));
        if (!any) break;  // fixed point => identical to reference while_loop
    }

    {
        uint4* pe = (uint4*)(g_edges + base);
#pragma unroll
        for (int q = 0; q < 4; q++)
            pe[q] = make_uint4(c[4*q+0], c[4*q+1], c[4*q+2], c[4*q+3]);
    }
}

// ---------------- XOR popcount reduction + sqrt + output -------------------
__global__ __launch_bounds__(256) void k_diff(float* out, int n) {
    const int totalv = (BATCH * WORDS_PER_IMG) / 4;    // uint4 per image-set
    const uint4* ea = (const uint4*)g_edges;
    const uint4* eb = ea + totalv;
    int idx = blockIdx.x * blockDim.x + threadIdx.x;
    int sum = 0;
    for (int i = idx; i < totalv; i += gridDim.x * blockDim.x) {
        uint4 a = ea[i], d = eb[i];
        sum += __popc(a.x ^ d.x) + __popc(a.y ^ d.y)
             + __popc(a.z ^ d.z) + __popc(a.w ^ d.w);
    }
#pragma unroll
    for (int o = 16; o > 0; o >>= 1) sum += __shfl_down_sync(0xffffffffu, sum, o);
    __shared__ int wsum[8];
    int lane = threadIdx.x & 31, wq = threadIdx.x >> 5;
    if (lane == 0) wsum[wq] = sum;
    __syncthreads();
    if (threadIdx.x == 0) {
        int s2 = 0;
#pragma unroll
        for (int i = 0; i < 8; i++) s2 += wsum[i];
        atomicAdd(&g_count, (unsigned)s2);
        __threadfence();
        unsigned ticket = atomicAdd(&g_done, 1u);
        if (ticket == gridDim.x - 1) {          // last block: finalize
            unsigned total = atomicAdd(&g_count, 0u);
            float v = sqrtf((float)total);
            for (int i = 0; i < n; i++) out[i] = v;
        }
    }
}

// ---------------- launch ---------------------------------------------------
extern "C" void kernel_launch(void* const* d_in, const int* in_sizes, int n_in,
                              void* d_out, int out_size) {
    const float* A = (const float*)d_in[0];
    const float* B = (const float*)d_in[1];

    size_t smemF = (size_t)(GRAY_ROWS * 256 + MAG_ROWS * MAGP2) * sizeof(__half2)
                 + (size_t)TILE_H * 128;                                      // ~74.5KB
    size_t smemH = (size_t)2 * HH * HPITCH * sizeof(uint32_t);                // 69,632B

    cudaFuncSetAttribute(k_frontend, cudaFuncAttributeMaxDynamicSharedMemorySize, (int)smemF);
    cudaFuncSetAttribute(k_hyster,   cudaFuncAttributeMaxDynamicSharedMemorySize, (int)smemH);

    k_frontend<<<dim3(HH / TILE_H, BATCH, 2), FTHREADS, smemF>>>(A, B);
    k_hyster<<<2 * BATCH, 512, smemH>>>();
    k_diff<<<256, 256>>>((float*)d_out, out_size);
}

// round 10
// speedup vs baseline: 1.0614x; 1.0614x over previous
#include <cuda_runtime.h>
#include <cuda_fp16.h>
#include <cstdint>

#define HH 512
#define WW 512
#define BATCH 32
#define WPR 16                       // uint32 words per row (512 bits)
#define WORDS_PER_IMG (HH * WPR)     // 8192 words = 32KB
#define TILE_H 32
#define GRAY_ROWS (TILE_H + 4)       // 36
#define MAG_ROWS  (TILE_H + 2)       // 34
#define MAGP 264                     // mag pitch in half2: 4 pad + 256 data + 4 pad
#define HPITCH 17                    // hysteresis exchange pitch (conflict-free)
#define FTHREADS 768

// ---------------- device scratch (no allocations allowed) ----------------
__device__ uint32_t g_weak  [2 * BATCH * WORDS_PER_IMG];
__device__ uint32_t g_strong[2 * BATCH * WORDS_PER_IMG];
__device__ uint32_t g_edges [2 * BATCH * WORDS_PER_IMG];
__device__ unsigned int g_count;
__device__ unsigned int g_done;

__device__ __forceinline__ __half2 u2h(unsigned u) { return *reinterpret_cast<__half2*>(&u); }
__device__ __forceinline__ unsigned h2u(__half2 h) { return *reinterpret_cast<unsigned*>(&h); }

// (lo = X.hi, hi = Y.lo): pair covering cols (c-1, c) when X is word before Y
__device__ __forceinline__ __half2 prhl(__half2 X, __half2 Y) {
    return __halves2half2(__high2half(X), __low2half(Y));
}

// nibble bits 0..3 -> bit positions 0,8,16,24
__device__ __forceinline__ unsigned nib8(unsigned x) {
    x &= 0xFu;
    x = (x | (x << 14)) & 0x00030003u;
    x = (x | (x << 7))  & 0x01010101u;
    return x;
}

__device__ __forceinline__ float grayq(float r, float g, float b) {
    // match XLA: ((0.299*R + 0.587*G) + 0.114*B), each op separately rounded
    float v = __fadd_rn(__fadd_rn(__fmul_rn(0.299f, r), __fmul_rn(0.587f, g)),
                        __fmul_rn(0.114f, b));
    return fminf(fmaxf(floorf(__fmul_rn(v, 255.0f)), 0.0f), 255.0f);
}

// classification for one half2 pair of (gx,gy): 2-bit classes for both px
__device__ __forceinline__ int classify2(__half2 gx2, __half2 gy2) {
    float2 gxf = __half22float2(gx2);
    float2 gyf = __half22float2(gy2);
    float ax0 = fabsf(gxf.x), ay0 = fabsf(gyf.x);
    float ax1 = fabsf(gxf.y), ay1 = fabsf(gyf.y);
    bool h0 = ay0 <= __fmul_rn((float)0.4142135623730951, ax0);
    bool v0 = ay0 >= __fmul_rn((float)2.414213562373095,  ax0);
    bool s0 = __fmul_rn(gxf.x, gyf.x) >= 0.0f;
    bool h1 = ay1 <= __fmul_rn((float)0.4142135623730951, ax1);
    bool v1 = ay1 >= __fmul_rn((float)2.414213562373095,  ax1);
    bool s1 = __fmul_rn(gxf.y, gyf.y) >= 0.0f;
    int cls0 = h0 ? 0 : (v0 ? 1 : (s0 ? 2 : 3));
    int cls1 = h1 ? 0 : (v1 ? 1 : (s1 ? 2 : 3));
    return cls0 | (cls1 << 2);
}

// load 8-px word quad + boundary words from a gray row (reflect at edges)
__device__ __forceinline__ void grow8(const __half2* row, int c8,
                                      __half2* A, __half2& P, __half2& N) {
    uint4 q = *reinterpret_cast<const uint4*>(&row[4 * c8]);
    A[0] = u2h(q.x); A[1] = u2h(q.y); A[2] = u2h(q.z); A[3] = u2h(q.w);
    // only P.hi (col-1) and N.lo (col+8) are consumed; reflect: col -1 -> col 1 (=A0.hi),
    // col 512 -> col 510 (=A3.lo)
    P = (c8 > 0)  ? row[4 * c8 - 1] : A[0];
    N = (c8 < 63) ? row[4 * c8 + 4] : A[3];
}

// ---------------- fused gray -> sobel+class -> NMS -> threshold -> bitpack
__global__ __launch_bounds__(FTHREADS, 2) void k_frontend(const float* __restrict__ A,
                                                          const float* __restrict__ B) {
    extern __shared__ __half2 smem2[];
    __half2*  sg2 = smem2;                       // [GRAY_ROWS][256]
    __half2*  sm3 = smem2 + GRAY_ROWS * 256;     // [MAG_ROWS][MAGP]
    uint16_t* sdc = (uint16_t*)(smem2 + GRAY_ROWS * 256 + MAG_ROWS * MAGP); // [TILE_H][64]

    const int tid  = threadIdx.x;
    const int tile = blockIdx.x;
    const int b    = blockIdx.y;
    const int im   = blockIdx.z;
    const int r0   = tile * TILE_H;
    const float* img = (im == 0 ? A : B) + (size_t)b * 3 * HH * WW;

    if (tile == 0 && b == 0 && im == 0 && tid == 0) { g_count = 0u; g_done = 0u; }

    // Stage 1: quantized grayscale, 4 px/thread via float4, reflect rows (halo 2)
    for (int p = tid; p < GRAY_ROWS * 128; p += FTHREADS) {
        int rr = p >> 7, c4 = p & 127;
        int gr = r0 - 2 + rr;
        gr = gr < 0 ? -gr : (gr > HH - 1 ? 2 * (HH - 1) - gr : gr);
        const float4* base = (const float4*)(img + gr * WW) + c4;
        float4 r4 = base[0];
        float4 g4 = base[(HH * WW) / 4];
        float4 b4 = base[(2 * HH * WW) / 4];
        __half2 h01 = __floats2half2_rn(grayq(r4.x, g4.x, b4.x), grayq(r4.y, g4.y, b4.y));
        __half2 h23 = __floats2half2_rn(grayq(r4.z, g4.z, b4.z), grayq(r4.w, g4.w, b4.w));
        uint2 pk; pk.x = h2u(h01); pk.y = h2u(h23);
        *reinterpret_cast<uint2*>(&sg2[rr * 256 + 2 * c4]) = pk;
    }
    // zero the mag pads while waiting (no dependency on sg2)
    {
        uint4 z4; z4.x = z4.y = z4.z = z4.w = 0u;
        for (int r = tid; r < MAG_ROWS; r += FTHREADS) {
            *reinterpret_cast<uint4*>(&sm3[r * MAGP])       = z4;   // left pad (4 half2)
            *reinterpret_cast<uint4*>(&sm3[r * MAGP + 260]) = z4;   // right pad
        }
    }
    __syncthreads();

    // Stage 2: separable Sobel -> magnitude + direction class, 8 px/thread
    const __half2 two2 = __floats2half2_rn(2.0f, 2.0f);
    for (int p = tid; p < MAG_ROWS * 64; p += FTHREADS) {
        int rr = p >> 6, c8 = p & 63;
        int gr = r0 - 1 + rr;
        uint4 mg; mg.x = mg.y = mg.z = mg.w = 0u;
        if (gr >= 0 && gr < HH) {
            int sr = rr + 1;
            __half2 tA[4], tP, tN, mA[4], mP, mN, bA[4], bP, bN;
            grow8(sg2 + (sr - 1) * 256, c8, tA, tP, tN);
            grow8(sg2 +  sr      * 256, c8, mA, mP, mN);
            grow8(sg2 + (sr + 1) * 256, c8, bA, bP, bN);
            // column sums: V = t + 2m + b (for gx), U = b - t (for gy)
            __half2 V[6], U[6];   // 0 = P-word, 1..4 = A0..A3, 5 = N-word
            V[0] = __hfma2(two2, mP, __hadd2(tP, bP));  U[0] = __hsub2(bP, tP);
            V[5] = __hfma2(two2, mN, __hadd2(tN, bN));  U[5] = __hsub2(bN, tN);
#pragma unroll
            for (int k = 0; k < 4; k++) {
                V[k + 1] = __hfma2(two2, mA[k], __hadd2(tA[k], bA[k]));
                U[k + 1] = __hsub2(bA[k], tA[k]);
            }
            // shifted pair chains: S[k] = (V[k].hi, V[k+1].lo) covers cols (2k-1, 2k)
            __half2 S[5], T[5];
#pragma unroll
            for (int k = 0; k < 5; k++) { S[k] = prhl(V[k], V[k + 1]); T[k] = prhl(U[k], U[k + 1]); }
            int cb = 0;
#pragma unroll
            for (int k = 0; k < 4; k++) {
                __half2 gx2 = __hsub2(S[k + 1], S[k]);                       // V_{c+1}-V_{c-1}
                __half2 gy2 = __hfma2(two2, U[k + 1], __hadd2(T[k], T[k + 1])); // U_{c-1}+2U_c+U_{c+1}
                __half2 m2 = __hadd2(__habs2(gx2), __habs2(gy2));            // exact <= 2040
                (&mg.x)[k] = h2u(m2);
                if (rr >= 1 && rr <= TILE_H)
                    cb |= classify2(gx2, gy2) << (4 * k);
            }
            if (rr >= 1 && rr <= TILE_H)
                sdc[(rr - 1) * 64 + c8] = (uint16_t)cb;
        }
        *reinterpret_cast<uint4*>(&sm3[rr * MAGP + 4 + 4 * c8]) = mg;
    }
    __syncthreads();

    // Stage 3: NMS from cached mag+class + threshold + bitpack; 8 px/thread
    const int lane = tid & 31;
    const size_t obase = ((size_t)(im * BATCH + b)) * WORDS_PER_IMG;
    const __half2 h25 = __floats2half2_rn(25.0f, 25.0f);
    const __half2 h76 = __floats2half2_rn(76.0f, 76.0f);
    for (int pt = tid; pt < TILE_H * 64; pt += FTHREADS) {
        int rr = pt >> 6, c8 = pt & 63;        // rr, (c8 & 32) warp-uniform

        // load 3 mag rows: quad + boundary words (branch-free via pads)
        __half2 tQ[4], mQ[4], bQ[4], tS[5], mS[5], bS[5];
        {
            const __half2* rt = sm3 +  rr      * MAGP + 4 + 4 * c8;
            const __half2* rm = sm3 + (rr + 1) * MAGP + 4 + 4 * c8;
            const __half2* rb = sm3 + (rr + 2) * MAGP + 4 + 4 * c8;
            uint4 qt = *reinterpret_cast<const uint4*>(rt);
            uint4 qm = *reinterpret_cast<const uint4*>(rm);
            uint4 qb = *reinterpret_cast<const uint4*>(rb);
            tQ[0]=u2h(qt.x); tQ[1]=u2h(qt.y); tQ[2]=u2h(qt.z); tQ[3]=u2h(qt.w);
            mQ[0]=u2h(qm.x); mQ[1]=u2h(qm.y); mQ[2]=u2h(qm.z); mQ[3]=u2h(qm.w);
            bQ[0]=u2h(qb.x); bQ[1]=u2h(qb.y); bQ[2]=u2h(qb.z); bQ[3]=u2h(qb.w);
            __half2 tP = rt[-1], tN = rt[4];
            __half2 mP = rm[-1], mN = rm[4];
            __half2 bP = rb[-1], bN = rb[4];
            tS[0]=prhl(tP,tQ[0]); mS[0]=prhl(mP,mQ[0]); bS[0]=prhl(bP,bQ[0]);
#pragma unroll
            for (int k = 1; k < 4; k++) {
                tS[k]=prhl(tQ[k-1],tQ[k]); mS[k]=prhl(mQ[k-1],mQ[k]); bS[k]=prhl(bQ[k-1],bQ[k]);
            }
            tS[4]=prhl(tQ[3],tN); mS[4]=prhl(mQ[3],mN); bS[4]=prhl(bQ[3],bN);
        }

        int cb = sdc[rr * 64 + c8];
        unsigned wbyte = 0u, sbyte = 0u;
#pragma unroll
        for (int k = 0; k < 4; k++) {
            __half2 mC = mQ[k];
            unsigned kh = __hgt2_mask(mC, mS[k]) & __hge2_mask(mC, mS[k + 1]);
            unsigned kv = __hgt2_mask(mC, tQ[k]) & __hge2_mask(mC, bQ[k]);
            unsigned k1 = __hgt2_mask(mC, tS[k]) & __hge2_mask(mC, bS[k + 1]);
            unsigned k2 = __hgt2_mask(mC, tS[k + 1]) & __hge2_mask(mC, bS[k]);
            unsigned wm = __hgt2_mask(mC, h25);
            unsigned sm = __hgt2_mask(mC, h76);
            int c0 = (cb >> (4 * k)) & 3, c1 = (cb >> (4 * k + 2)) & 3;
            unsigned s0 = c0 == 0 ? kh : (c0 == 1 ? kv : (c0 == 2 ? k1 : k2));
            unsigned s1 = c1 == 0 ? kh : (c1 == 1 ? kv : (c1 == 2 ? k1 : k2));
            wbyte |= ((s0 & wm) & 1u) << (2 * k);
            wbyte |= (((s1 & wm) >> 16) & 1u) << (2 * k + 1);
            sbyte |= ((s0 & sm) & 1u) << (2 * k);
            sbyte |= (((s1 & sm) >> 16) & 1u) << (2 * k + 1);
        }

        unsigned bw[8], bs[8];
#pragma unroll
        for (int j = 0; j < 8; j++) {
            bw[j] = __ballot_sync(0xffffffffu, (wbyte >> j) & 1u);
            bs[j] = __ballot_sync(0xffffffffu, (sbyte >> j) & 1u);
        }
        if (lane < 16) {
            int k = lane & 7;
            bool is_st = lane >= 8;
            unsigned word = 0u;
#pragma unroll
            for (int j = 0; j < 8; j++) {
                unsigned x = is_st ? bs[j] : bw[j];
                word |= nib8(x >> (4 * k)) << j;
            }
            uint32_t* dst = is_st ? (g_strong + obase) : (g_weak + obase);
            int wbase = (c8 & 32) >> 2;            // warp's first word index (0 or 8)
            dst[(size_t)(r0 + rr) * WPR + wbase + k] = word;
        }
    }
}

// ---------------- bitwise hysteresis: 1 CTA/image, 1 row/thread, regs-resident
__global__ __launch_bounds__(512) void k_hyster() {
    extern __shared__ uint32_t sbuf[];   // 2 buffers of [512][HPITCH]
    const int t = threadIdx.x;           // row index 0..511
    const int im = blockIdx.x >> 5, b = blockIdx.x & 31;
    const size_t base = ((size_t)(im * BATCH + b)) * WORDS_PER_IMG + (size_t)t * WPR;

    uint32_t w[WPR], s[WPR], c[WPR];
    {
        const uint4* pw = (const uint4*)(g_weak + base);
        const uint4* ps = (const uint4*)(g_strong + base);
#pragma unroll
        for (int q = 0; q < 4; q++) {
            uint4 a = pw[q];
            w[4*q+0]=a.x; w[4*q+1]=a.y; w[4*q+2]=a.z; w[4*q+3]=a.w;
            uint4 d = ps[q];
            s[4*q+0]=d.x; s[4*q+1]=d.y; s[4*q+2]=d.z; s[4*q+3]=d.w;
        }
    }
#pragma unroll
    for (int i = 0; i < WPR; i++) c[i] = s[i];

    uint32_t* b0 = sbuf;
    uint32_t* b1 = sbuf + HH * HPITCH;
#pragma unroll
    for (int i = 0; i < WPR; i++) b0[t * HPITCH + i] = c[i];
    __syncthreads();

    for (int it = 0; it < 64; ++it) {
        const uint32_t* rd = (it & 1) ? b1 : b0;
        uint32_t*       wr = (it & 1) ? b0 : b1;
        const uint32_t* pu = rd + (t - 1) * HPITCH;
        const uint32_t* pd = rd + (t + 1) * HPITCH;
        uint32_t vor[WPR];
#pragma unroll
        for (int i = 0; i < WPR; i++) {
            uint32_t u = (t > 0)      ? pu[i] : 0u;
            uint32_t d = (t < HH - 1) ? pd[i] : 0u;
            vor[i] = u | d | c[i];               // vertical max (separable)
        }
        uint32_t ch = 0u;
#pragma unroll
        for (int i = 0; i < WPR; i++) {
            uint32_t lo = (i > 0)       ? vor[i - 1] : 0u;
            uint32_t hi = (i < WPR - 1) ? vor[i + 1] : 0u;
            uint32_t l = __funnelshift_l(lo, vor[i], 1);   // col-1 values
            uint32_t r = __funnelshift_r(vor[i], hi, 1);   // col+1 values
            uint32_t d3 = l | vor[i] | r;                  // 3x3 dilate done
            uint32_t nv = (d3 & w[i]) | s[i];
            ch |= nv ^ c[i];
            c[i] = nv;
            wr[t * HPITCH + i] = nv;
        }
        int any = __syncthreads_or((int)(ch != 0u));
        if (!any) break;  // fixed point => identical to reference while_loop
    }

    {
        uint4* pe = (uint4*)(g_edges + base);
#pragma unroll
        for (int q = 0; q < 4; q++)
            pe[q] = make_uint4(c[4*q+0], c[4*q+1], c[4*q+2], c[4*q+3]);
    }
}

// ---------------- XOR popcount reduction + sqrt + output -------------------
__global__ __launch_bounds__(256) void k_diff(float* out, int n) {
    const int totalv = (BATCH * WORDS_PER_IMG) / 4;    // uint4 per image-set
    const uint4* ea = (const uint4*)g_edges;
    const uint4* eb = ea + totalv;
    int idx = blockIdx.x * blockDim.x + threadIdx.x;
    int sum = 0;
    for (int i = idx; i < totalv; i += gridDim.x * blockDim.x) {
        uint4 a = ea[i], d = eb[i];
        sum += __popc(a.x ^ d.x) + __popc(a.y ^ d.y)
             + __popc(a.z ^ d.z) + __popc(a.w ^ d.w);
    }
#pragma unroll
    for (int o = 16; o > 0; o >>= 1) sum += __shfl_down_sync(0xffffffffu, sum, o);
    __shared__ int wsum[8];
    int lane = threadIdx.x & 31, wq = threadIdx.x >> 5;
    if (lane == 0) wsum[wq] = sum;
    __syncthreads();
    if (threadIdx.x == 0) {
        int s2 = 0;
#pragma unroll
        for (int i = 0; i < 8; i++) s2 += wsum[i];
        atomicAdd(&g_count, (unsigned)s2);
        __threadfence();
        unsigned ticket = atomicAdd(&g_done, 1u);
        if (ticket == gridDim.x - 1) {          // last block: finalize
            unsigned total = atomicAdd(&g_count, 0u);
            float v = sqrtf((float)total);
            for (int i = 0; i < n; i++) out[i] = v;
        }
    }
}

// ---------------- launch ---------------------------------------------------
extern "C" void kernel_launch(void* const* d_in, const int* in_sizes, int n_in,
                              void* d_out, int out_size) {
    const float* A = (const float*)d_in[0];
    const float* B = (const float*)d_in[1];

    size_t smemF = (size_t)(GRAY_ROWS * 256 + MAG_ROWS * MAGP) * sizeof(__half2)
                 + (size_t)TILE_H * 64 * sizeof(uint16_t);                    // ~75.1KB
    size_t smemH = (size_t)2 * HH * HPITCH * sizeof(uint32_t);                // 69,632B

    cudaFuncSetAttribute(k_frontend, cudaFuncAttributeMaxDynamicSharedMemorySize, (int)smemF);
    cudaFuncSetAttribute(k_hyster,   cudaFuncAttributeMaxDynamicSharedMemorySize, (int)smemH);

    k_frontend<<<dim3(HH / TILE_H, BATCH, 2), FTHREADS, smemF>>>(A, B);
    k_hyster<<<2 * BATCH, 512, smemH>>>();
    k_diff<<<256, 256>>>((float*)d_out, out_size);
}

// round 12
// speedup vs baseline: 1.1120x; 1.0476x over previous
#include <cuda_runtime.h>
#include <cuda_fp16.h>
#include <cstdint>

#define HH 512
#define WW 512
#define BATCH 32
#define WPR 16                       // uint32 words per row (512 bits)
#define WORDS_PER_IMG (HH * WPR)     // 8192 words = 32KB
#define TILE_H 32
#define GRAY_ROWS (TILE_H + 4)       // 36
#define MAG_ROWS  (TILE_H + 2)       // 34
#define MAGP2 260                    // mag pitch in half2 (2 zero half2 pads each side)
#define HPITCH 17                    // hysteresis exchange pitch (conflict-free)
#define FTHREADS 768

// ---------------- device scratch (no allocations allowed) ----------------
__device__ uint32_t g_weak  [2 * BATCH * WORDS_PER_IMG];
__device__ uint32_t g_strong[2 * BATCH * WORDS_PER_IMG];
__device__ uint32_t g_edges [BATCH * WORDS_PER_IMG];     // im=0 edges only
__device__ unsigned int g_flag[BATCH];
__device__ unsigned int g_count;
__device__ unsigned int g_done;

__device__ __forceinline__ unsigned spread4(unsigned x) {   // bit i -> bit 4i (8 bits in)
    x &= 0xFFu;
    x = (x | (x << 12)) & 0x000F000Fu;
    x = (x | (x << 6))  & 0x03030303u;
    x = (x | (x << 3))  & 0x11111111u;
    return x;
}

__device__ __forceinline__ __half2 u2h(unsigned u) { return *reinterpret_cast<__half2*>(&u); }
__device__ __forceinline__ unsigned h2u(__half2 h) { return *reinterpret_cast<unsigned*>(&h); }

// pair (X.hi, Y.lo): covers cols (c-1, c) when X = word before Y
__device__ __forceinline__ __half2 prhl(__half2 X, __half2 Y) {
    return __halves2half2(__high2half(X), __low2half(Y));
}

// gray quad: for 4 px (word pair w0=2*c4, w1=2*c4+1), reflect at image edges.
__device__ __forceinline__ void gquad(const __half2* row, int c4,
                                      __half2& L, __half2& C0, __half2& R,
                                      __half2& C1, __half2& R1) {
    uint2 ab = *reinterpret_cast<const uint2*>(&row[2 * c4]);
    __half2 A = u2h(ab.x), B = u2h(ab.y);
    __half2 P = (c4 > 0)   ? row[2 * c4 - 1] : __lowhigh2highlow(A);
    __half2 N = (c4 < 127) ? row[2 * c4 + 2] : __lowhigh2highlow(B);
    L  = (c4 > 0)   ? prhl(P, A) : P;    // reflect: (g1,g0)
    R1 = (c4 < 127) ? prhl(B, N) : N;    // reflect: (g511,g510)
    C0 = A; C1 = B;
    R  = prhl(A, B);
}

// mag quad: zero-padded (2 words each side), branch-free
__device__ __forceinline__ void mquad(const __half2* row, int c4,
                                      __half2& L, __half2& C0, __half2& R,
                                      __half2& C1, __half2& R1) {
    uint2 ab = *reinterpret_cast<const uint2*>(&row[2 * c4 + 2]);
    __half2 A = u2h(ab.x), B = u2h(ab.y);
    __half2 P = row[2 * c4 + 1];
    __half2 N = row[2 * c4 + 4];
    L = prhl(P, A); R = prhl(A, B); R1 = prhl(B, N);
    C0 = A; C1 = B;
}

// Sobel on half2 triples (all values exact integers -> exact in fp16)
__device__ __forceinline__ void sobel2(__half2 tL, __half2 tC, __half2 tR,
                                       __half2 mL, __half2 mR,
                                       __half2 bL, __half2 bC, __half2 bR,
                                       __half2& gx2, __half2& gy2) {
    const __half2 two2 = __floats2half2_rn(2.0f, 2.0f);
    __half2 dt = __hsub2(tR, tL);
    __half2 dm = __hsub2(mR, mL);
    __half2 db = __hsub2(bR, bL);
    gx2 = __hadd2(__hfma2(two2, dm, dt), db);
    __half2 st = __hfma2(two2, tC, __hadd2(tL, tR));
    __half2 sb = __hfma2(two2, bC, __hadd2(bL, bR));
    gy2 = __hsub2(sb, st);
}

__device__ __forceinline__ float grayq(float r, float g, float b) {
    // match XLA: ((0.299*R + 0.587*G) + 0.114*B), each op separately rounded
    float v = __fadd_rn(__fadd_rn(__fmul_rn(0.299f, r), __fmul_rn(0.587f, g)),
                        __fmul_rn(0.114f, b));
    return fminf(fmaxf(floorf(__fmul_rn(v, 255.0f)), 0.0f), 255.0f);
}

// classification for one half2 pair of (gx,gy): 2-bit classes for both px
__device__ __forceinline__ int classify2(__half2 gx2, __half2 gy2) {
    float2 gxf = __half22float2(gx2);
    float2 gyf = __half22float2(gy2);
    float ax0 = fabsf(gxf.x), ay0 = fabsf(gyf.x);
    float ax1 = fabsf(gxf.y), ay1 = fabsf(gyf.y);
    bool h0 = ay0 <= __fmul_rn((float)0.4142135623730951, ax0);
    bool v0 = ay0 >= __fmul_rn((float)2.414213562373095,  ax0);
    bool s0 = __fmul_rn(gxf.x, gyf.x) >= 0.0f;
    bool h1 = ay1 <= __fmul_rn((float)0.4142135623730951, ax1);
    bool v1 = ay1 >= __fmul_rn((float)2.414213562373095,  ax1);
    bool s1 = __fmul_rn(gxf.y, gyf.y) >= 0.0f;
    int cls0 = h0 ? 0 : (v0 ? 1 : (s0 ? 2 : 3));
    int cls1 = h1 ? 0 : (v1 ? 1 : (s1 ? 2 : 3));
    return cls0 | (cls1 << 2);
}

// ---------------- fused gray -> sobel+class -> NMS -> threshold -> bitpack
// (exact R8 structure: 768 threads, 2 CTAs/SM, 4 px/thread)
__global__ __launch_bounds__(FTHREADS, 2) void k_frontend(const float* __restrict__ A,
                                                          const float* __restrict__ B) {
    extern __shared__ __half2 smem2[];
    __half2* sg2 = smem2;                      // [GRAY_ROWS][256]
    __half2* sm2 = smem2 + GRAY_ROWS * 256;    // [MAG_ROWS][MAGP2]
    uint8_t* sdc = (uint8_t*)(smem2 + GRAY_ROWS * 256 + MAG_ROWS * MAGP2); // [TILE_H][128]

    const int tid  = threadIdx.x;
    const int tile = blockIdx.x;
    const int b    = blockIdx.y;
    const int im   = blockIdx.z;
    const int r0   = tile * TILE_H;
    const float* img = (im == 0 ? A : B) + (size_t)b * 3 * HH * WW;

    if (tile == 0 && b == 0 && im == 0 && tid < 32) {
        g_flag[tid] = 0u;
        if (tid == 0) { g_count = 0u; g_done = 0u; }
    }

    // Stage 1: quantized grayscale, 4 px/thread via float4, reflect rows (halo 2)
    for (int p = tid; p < GRAY_ROWS * 128; p += FTHREADS) {
        int rr = p >> 7, c4 = p & 127;
        int gr = r0 - 2 + rr;
        gr = gr < 0 ? -gr : (gr > HH - 1 ? 2 * (HH - 1) - gr : gr);
        const float4* base = (const float4*)(img + gr * WW) + c4;
        float4 r4 = base[0];
        float4 g4 = base[(HH * WW) / 4];
        float4 b4 = base[(2 * HH * WW) / 4];
        __half2 h01 = __floats2half2_rn(grayq(r4.x, g4.x, b4.x), grayq(r4.y, g4.y, b4.y));
        __half2 h23 = __floats2half2_rn(grayq(r4.z, g4.z, b4.z), grayq(r4.w, g4.w, b4.w));
        uint2 pk; pk.x = h2u(h01); pk.y = h2u(h23);
        *reinterpret_cast<uint2*>(&sg2[rr * 256 + 2 * c4]) = pk;
    }
    __syncthreads();

    // Stage 2: magnitude + direction class, 4 px/thread
    for (int p = tid; p < MAG_ROWS * 128; p += FTHREADS) {
        int rr = p >> 7, c4 = p & 127;
        int gr = r0 - 1 + rr;
        __half2 m20 = __floats2half2_rn(0.0f, 0.0f);
        __half2 m21 = m20;
        if (gr >= 0 && gr < HH) {
            int sr = rr + 1;
            __half2 tL, tC0, tR, tC1, tR1;
            __half2 mL, mC0, mR, mC1, mR1;
            __half2 bL, bC0, bR, bC1, bR1;
            gquad(sg2 + (sr - 1) * 256, c4, tL, tC0, tR, tC1, tR1);
            gquad(sg2 +  sr      * 256, c4, mL, mC0, mR, mC1, mR1);
            gquad(sg2 + (sr + 1) * 256, c4, bL, bC0, bR, bC1, bR1);
            __half2 gx0, gy0, gx1, gy1;
            sobel2(tL, tC0, tR,  mL, mR,  bL, bC0, bR,  gx0, gy0);   // pair0
            sobel2(tR, tC1, tR1, mR, mR1, bR, bC1, bR1, gx1, gy1);   // pair1 (L1=R0)
            m20 = __hadd2(__habs2(gx0), __habs2(gy0));   // <= 2040, exact
            m21 = __hadd2(__habs2(gx1), __habs2(gy1));
            if (rr >= 1 && rr <= TILE_H) {
                int cb = classify2(gx0, gy0) | (classify2(gx1, gy1) << 4);
                sdc[(rr - 1) * 128 + c4] = (uint8_t)cb;
            }
        }
        uint2 pk; pk.x = h2u(m20); pk.y = h2u(m21);
        *reinterpret_cast<uint2*>(&sm2[rr * MAGP2 + 2 * c4 + 2]) = pk;
    }
    {
        uint2 z2; z2.x = 0u; z2.y = 0u;
        for (int r = tid; r < MAG_ROWS; r += FTHREADS) {
            *reinterpret_cast<uint2*>(&sm2[r * MAGP2])       = z2;
            *reinterpret_cast<uint2*>(&sm2[r * MAGP2 + 258]) = z2;
        }
    }
    __syncthreads();

    // Stage 3: NMS from cached mag+class + threshold + bitpack; 4 px/thread
    const int lane = tid & 31;
    const size_t obase = ((size_t)(im * BATCH + b)) * WORDS_PER_IMG;
    const __half2 h25 = __floats2half2_rn(25.0f, 25.0f);
    const __half2 h76 = __floats2half2_rn(76.0f, 76.0f);
    for (int pt = tid; pt < TILE_H * 128; pt += FTHREADS) {
        int rr = pt >> 7, c4 = pt & 127;       // rr uniform per warp

        __half2 tL, tC0, tR, tC1, tR1;
        __half2 mL, mC0, mR, mC1, mR1;
        __half2 bL, bC0, bR, bC1, bR1;
        mquad(sm2 +  rr      * MAGP2, c4, tL, tC0, tR, tC1, tR1);
        mquad(sm2 + (rr + 1) * MAGP2, c4, mL, mC0, mR, mC1, mR1);
        mquad(sm2 + (rr + 2) * MAGP2, c4, bL, bC0, bR, bC1, bR1);

        // pair0 (cols c, c+1)
        unsigned kh0 = __hgt2_mask(mC0, mL)  & __hge2_mask(mC0, mR);
        unsigned kv0 = __hgt2_mask(mC0, tC0) & __hge2_mask(mC0, bC0);
        unsigned k10 = __hgt2_mask(mC0, tL)  & __hge2_mask(mC0, bR);
        unsigned k20 = __hgt2_mask(mC0, tR)  & __hge2_mask(mC0, bL);
        unsigned wm0 = __hgt2_mask(mC0, h25);
        unsigned sm0 = __hgt2_mask(mC0, h76);
        // pair1 (cols c+2, c+3)
        unsigned kh1 = __hgt2_mask(mC1, mR)  & __hge2_mask(mC1, mR1);
        unsigned kv1 = __hgt2_mask(mC1, tC1) & __hge2_mask(mC1, bC1);
        unsigned k11 = __hgt2_mask(mC1, tR)  & __hge2_mask(mC1, bR1);
        unsigned k21 = __hgt2_mask(mC1, tR1) & __hge2_mask(mC1, bR);
        unsigned wm1 = __hgt2_mask(mC1, h25);
        unsigned sm1 = __hgt2_mask(mC1, h76);

        int cb = sdc[rr * 128 + c4];
        int c0 = cb & 3, c1 = (cb >> 2) & 3, c2_ = (cb >> 4) & 3, c3 = (cb >> 6) & 3;
        unsigned s0 = c0 == 0 ? kh0 : (c0 == 1 ? kv0 : (c0 == 2 ? k10 : k20));
        unsigned s1 = c1 == 0 ? kh0 : (c1 == 1 ? kv0 : (c1 == 2 ? k10 : k20));
        unsigned s2 = c2_ == 0 ? kh1 : (c2_ == 1 ? kv1 : (c2_ == 2 ? k11 : k21));
        unsigned s3 = c3 == 0 ? kh1 : (c3 == 1 ? kv1 : (c3 == 2 ? k11 : k21));
        bool wk0 =  (s0 & wm0)         & 1u;
        bool st0 =  (s0 & sm0)         & 1u;
        bool wk1 = ((s1 & wm0) >> 16)  & 1u;
        bool st1 = ((s1 & sm0) >> 16)  & 1u;
        bool wk2 =  (s2 & wm1)         & 1u;
        bool st2 =  (s2 & sm1)         & 1u;
        bool wk3 = ((s3 & wm1) >> 16)  & 1u;
        bool st3 = ((s3 & sm1) >> 16)  & 1u;

        unsigned bw0 = __ballot_sync(0xffffffffu, wk0);
        unsigned bw1 = __ballot_sync(0xffffffffu, wk1);
        unsigned bw2 = __ballot_sync(0xffffffffu, wk2);
        unsigned bw3 = __ballot_sync(0xffffffffu, wk3);
        unsigned bs0 = __ballot_sync(0xffffffffu, st0);
        unsigned bs1 = __ballot_sync(0xffffffffu, st1);
        unsigned bs2 = __ballot_sync(0xffffffffu, st2);
        unsigned bs3 = __ballot_sync(0xffffffffu, st3);

        if (lane < 8) {
            int m = lane & 3;
            bool is_st = lane >= 4;          // lanes 0-3 weak, 4-7 strong
            unsigned x0 = is_st ? bs0 : bw0;
            unsigned x1 = is_st ? bs1 : bw1;
            unsigned x2 = is_st ? bs2 : bw2;
            unsigned x3 = is_st ? bs3 : bw3;
            int sh = 8 * m;
            unsigned wordv = spread4(x0 >> sh) | (spread4(x1 >> sh) << 1)
                           | (spread4(x2 >> sh) << 2) | (spread4(x3 >> sh) << 3);
            uint32_t* dst = is_st ? (g_strong + obase) : (g_weak + obase);
            int wbase = (c4 & ~31) >> 3;           // warp's first word index
            dst[(size_t)(r0 + rr) * WPR + wbase + m] = wordv;
        }
    }
}

// ---------------- hysteresis + fused diff ----------------------------------
// 1 CTA per (image,batch); im=0 publishes edges, im=1 diffs in-register.
__global__ __launch_bounds__(512) void k_hyster(float* out, int n) {
    extern __shared__ uint32_t sbuf[];   // 2 buffers of [512][HPITCH]
    const int t = threadIdx.x;           // row index 0..511
    const int im = blockIdx.x >> 5, b = blockIdx.x & 31;
    const size_t base = ((size_t)(im * BATCH + b)) * WORDS_PER_IMG + (size_t)t * WPR;

    uint32_t w[WPR], s[WPR], c[WPR];
    {
        const uint4* pw = (const uint4*)(g_weak + base);
        const uint4* ps = (const uint4*)(g_strong + base);
#pragma unroll
        for (int q = 0; q < 4; q++) {
            uint4 a = pw[q];
            w[4*q+0]=a.x; w[4*q+1]=a.y; w[4*q+2]=a.z; w[4*q+3]=a.w;
            uint4 d = ps[q];
            s[4*q+0]=d.x; s[4*q+1]=d.y; s[4*q+2]=d.z; s[4*q+3]=d.w;
        }
    }
#pragma unroll
    for (int i = 0; i < WPR; i++) c[i] = s[i];

    uint32_t* b0 = sbuf;
    uint32_t* b1 = sbuf + HH * HPITCH;
#pragma unroll
    for (int i = 0; i < WPR; i++) b0[t * HPITCH + i] = c[i];
    __syncthreads();

    for (int it = 0; it < 64; ++it) {
        const uint32_t* rd = (it & 1) ? b1 : b0;
        uint32_t*       wr = (it & 1) ? b0 : b1;
        const uint32_t* pu = rd + (t - 1) * HPITCH;
        const uint32_t* pd = rd + (t + 1) * HPITCH;
        uint32_t vor[WPR];
#pragma unroll
        for (int i = 0; i < WPR; i++) {
            uint32_t u = (t > 0)      ? pu[i] : 0u;
            uint32_t d = (t < HH - 1) ? pd[i] : 0u;
            vor[i] = u | d | c[i];               // vertical max (separable)
        }
        uint32_t ch = 0u;
#pragma unroll
        for (int i = 0; i < WPR; i++) {
            uint32_t lo = (i > 0)       ? vor[i - 1] : 0u;
            uint32_t hi = (i < WPR - 1) ? vor[i + 1] : 0u;
            uint32_t l = __funnelshift_l(lo, vor[i], 1);   // col-1 values
            uint32_t r = __funnelshift_r(vor[i], hi, 1);   // col+1 values
            uint32_t d3 = l | vor[i] | r;                  // 3x3 dilate done
            uint32_t nv = (d3 & w[i]) | s[i];
            ch |= nv ^ c[i];
            c[i] = nv;
            wr[t * HPITCH + i] = nv;
        }
        int any = __syncthreads_or((int)(ch != 0u));
        if (!any) break;  // fixed point => identical to reference while_loop
    }

    if (im == 0) {
        // publish edges + release flag
        uint4* pe = (uint4*)(g_edges + (size_t)b * WORDS_PER_IMG + (size_t)t * WPR);
#pragma unroll
        for (int q = 0; q < 4; q++)
            pe[q] = make_uint4(c[4*q+0], c[4*q+1], c[4*q+2], c[4*q+3]);
        __threadfence();
        __syncthreads();
        if (t == 0) atomicExch(&g_flag[b], 1u);
    } else {
        // acquire partner edges, then diff in-register
        if (t == 0) {
            while (atomicAdd(&g_flag[b], 0u) == 0u) __nanosleep(64);
            __threadfence();
        }
        __syncthreads();
        __threadfence();
        const uint4* pe = (const uint4*)(g_edges + (size_t)b * WORDS_PER_IMG + (size_t)t * WPR);
        int sum = 0;
#pragma unroll
        for (int q = 0; q < 4; q++) {
            uint4 e = pe[q];
            sum += __popc(c[4*q+0] ^ e.x) + __popc(c[4*q+1] ^ e.y)
                 + __popc(c[4*q+2] ^ e.z) + __popc(c[4*q+3] ^ e.w);
        }
#pragma unroll
        for (int o = 16; o > 0; o >>= 1) sum += __shfl_down_sync(0xffffffffu, sum, o);
        __syncthreads();                       // sbuf reuse safe
        int* ws = (int*)sbuf;
        if ((t & 31) == 0) ws[t >> 5] = sum;
        __syncthreads();
        if (t == 0) {
            int s2 = 0;
#pragma unroll
            for (int i = 0; i < 16; i++) s2 += ws[i];
            atomicAdd(&g_count, (unsigned)s2);
            __threadfence();
            unsigned ticket = atomicAdd(&g_done, 1u);
            if (ticket == BATCH - 1) {          // last diff block finalizes
                float v = sqrtf((float)atomicAdd(&g_count, 0u));
                for (int i = 0; i < n; i++) out[i] = v;
            }
        }
    }
}

// ---------------- launch ---------------------------------------------------
extern "C" void kernel_launch(void* const* d_in, const int* in_sizes, int n_in,
                              void* d_out, int out_size) {
    const float* A = (const float*)d_in[0];
    const float* B = (const float*)d_in[1];

    size_t smemF = (size_t)(GRAY_ROWS * 256 + MAG_ROWS * MAGP2) * sizeof(__half2)
                 + (size_t)TILE_H * 128;                                      // ~74.5KB
    size_t smemH = (size_t)2 * HH * HPITCH * sizeof(uint32_t);                // 69,632B

    cudaFuncSetAttribute(k_frontend, cudaFuncAttributeMaxDynamicSharedMemorySize, (int)smemF);
    cudaFuncSetAttribute(k_hyster,   cudaFuncAttributeMaxDynamicSharedMemorySize, (int)smemH);

    k_frontend<<<dim3(HH / TILE_H, BATCH, 2), FTHREADS, smemF>>>(A, B);
    k_hyster<<<2 * BATCH, 512, smemH>>>((float*)d_out, out_size);
}

// round 13
// speedup vs baseline: 1.1843x; 1.0650x over previous
#include <cuda_runtime.h>
#include <cuda_fp16.h>
#include <cstdint>

#define HH 512
#define WW 512
#define BATCH 32
#define WPR 16                       // uint32 words per row (512 bits)
#define WORDS_PER_IMG (HH * WPR)     // 8192 words = 32KB
#define TILE_H 32
#define GRAY_ROWS (TILE_H + 4)       // 36
#define MAG_ROWS  (TILE_H + 2)       // 34
#define MAGP2 260                    // mag pitch in half2 (2 zero half2 pads each side)
#define HPITCH 20                    // hysteresis pitch: 16 data + 4 pad, 80B rows (16B aligned, conflict-free)
#define FTHREADS 768

// ---------------- device scratch (no allocations allowed) ----------------
__device__ uint32_t g_weak  [2 * BATCH * WORDS_PER_IMG];
__device__ uint32_t g_strong[2 * BATCH * WORDS_PER_IMG];
__device__ uint32_t g_edges [BATCH * WORDS_PER_IMG];     // im=0 edges only
__device__ unsigned int g_flag[BATCH];
__device__ unsigned int g_count;
__device__ unsigned int g_done;

__device__ __forceinline__ unsigned spread4(unsigned x) {   // bit i -> bit 4i (8 bits in)
    x &= 0xFFu;
    x = (x | (x << 12)) & 0x000F000Fu;
    x = (x | (x << 6))  & 0x03030303u;
    x = (x | (x << 3))  & 0x11111111u;
    return x;
}

__device__ __forceinline__ __half2 u2h(unsigned u) { return *reinterpret_cast<__half2*>(&u); }
__device__ __forceinline__ unsigned h2u(__half2 h) { return *reinterpret_cast<unsigned*>(&h); }

// pair (X.hi, Y.lo): covers cols (c-1, c) when X = word before Y
__device__ __forceinline__ __half2 prhl(__half2 X, __half2 Y) {
    return __halves2half2(__high2half(X), __low2half(Y));
}

// gray quad: for 4 px (word pair w0=2*c4, w1=2*c4+1), reflect at image edges.
__device__ __forceinline__ void gquad(const __half2* row, int c4,
                                      __half2& L, __half2& C0, __half2& R,
                                      __half2& C1, __half2& R1) {
    uint2 ab = *reinterpret_cast<const uint2*>(&row[2 * c4]);
    __half2 A = u2h(ab.x), B = u2h(ab.y);
    __half2 P = (c4 > 0)   ? row[2 * c4 - 1] : __lowhigh2highlow(A);
    __half2 N = (c4 < 127) ? row[2 * c4 + 2] : __lowhigh2highlow(B);
    L  = (c4 > 0)   ? prhl(P, A) : P;    // reflect: (g1,g0)
    R1 = (c4 < 127) ? prhl(B, N) : N;    // reflect: (g511,g510)
    C0 = A; C1 = B;
    R  = prhl(A, B);
}

// mag quad: zero-padded (2 words each side), branch-free
__device__ __forceinline__ void mquad(const __half2* row, int c4,
                                      __half2& L, __half2& C0, __half2& R,
                                      __half2& C1, __half2& R1) {
    uint2 ab = *reinterpret_cast<const uint2*>(&row[2 * c4 + 2]);
    __half2 A = u2h(ab.x), B = u2h(ab.y);
    __half2 P = row[2 * c4 + 1];
    __half2 N = row[2 * c4 + 4];
    L = prhl(P, A); R = prhl(A, B); R1 = prhl(B, N);
    C0 = A; C1 = B;
}

// Sobel on half2 triples (all values exact integers -> exact in fp16)
__device__ __forceinline__ void sobel2(__half2 tL, __half2 tC, __half2 tR,
                                       __half2 mL, __half2 mR,
                                       __half2 bL, __half2 bC, __half2 bR,
                                       __half2& gx2, __half2& gy2) {
    const __half2 two2 = __floats2half2_rn(2.0f, 2.0f);
    __half2 dt = __hsub2(tR, tL);
    __half2 dm = __hsub2(mR, mL);
    __half2 db = __hsub2(bR, bL);
    gx2 = __hadd2(__hfma2(two2, dm, dt), db);
    __half2 st = __hfma2(two2, tC, __hadd2(tL, tR));
    __half2 sb = __hfma2(two2, bC, __hadd2(bL, bR));
    gy2 = __hsub2(sb, st);
}

__device__ __forceinline__ float grayq(float r, float g, float b) {
    // match XLA: ((0.299*R + 0.587*G) + 0.114*B), each op separately rounded
    float v = __fadd_rn(__fadd_rn(__fmul_rn(0.299f, r), __fmul_rn(0.587f, g)),
                        __fmul_rn(0.114f, b));
    return fminf(fmaxf(floorf(__fmul_rn(v, 255.0f)), 0.0f), 255.0f);
}

// classification for one half2 pair of (gx,gy): 2-bit classes for both px
__device__ __forceinline__ int classify2(__half2 gx2, __half2 gy2) {
    float2 gxf = __half22float2(gx2);
    float2 gyf = __half22float2(gy2);
    float ax0 = fabsf(gxf.x), ay0 = fabsf(gyf.x);
    float ax1 = fabsf(gxf.y), ay1 = fabsf(gyf.y);
    bool h0 = ay0 <= __fmul_rn((float)0.4142135623730951, ax0);
    bool v0 = ay0 >= __fmul_rn((float)2.414213562373095,  ax0);
    bool s0 = __fmul_rn(gxf.x, gyf.x) >= 0.0f;
    bool h1 = ay1 <= __fmul_rn((float)0.4142135623730951, ax1);
    bool v1 = ay1 >= __fmul_rn((float)2.414213562373095,  ax1);
    bool s1 = __fmul_rn(gxf.y, gyf.y) >= 0.0f;
    int cls0 = h0 ? 0 : (v0 ? 1 : (s0 ? 2 : 3));
    int cls1 = h1 ? 0 : (v1 ? 1 : (s1 ? 2 : 3));
    return cls0 | (cls1 << 2);
}

// ---------------- fused gray -> sobel+class -> NMS -> threshold -> bitpack
__global__ __launch_bounds__(FTHREADS, 2) void k_frontend(const float* __restrict__ A,
                                                          const float* __restrict__ B) {
    extern __shared__ __half2 smem2[];
    __half2* sg2 = smem2;                      // [GRAY_ROWS][256]
    __half2* sm2 = smem2 + GRAY_ROWS * 256;    // [MAG_ROWS][MAGP2]
    uint8_t* sdc = (uint8_t*)(smem2 + GRAY_ROWS * 256 + MAG_ROWS * MAGP2); // [TILE_H][128]

    const int tid  = threadIdx.x;
    const int tile = blockIdx.x;
    const int b    = blockIdx.y;
    const int im   = blockIdx.z;
    const int r0   = tile * TILE_H;
    const float* img = (im == 0 ? A : B) + (size_t)b * 3 * HH * WW;

    if (tile == 0 && b == 0 && im == 0 && tid < 32) {
        g_flag[tid] = 0u;
        if (tid == 0) { g_count = 0u; g_done = 0u; }
    }

    // Stage 1: grayscale, fixed 6 trips (36*128 = 6*768), fully unrolled
#pragma unroll
    for (int k = 0; k < 6; k++) {
        int p = tid + k * FTHREADS;
        int rr = p >> 7, c4 = p & 127;
        int gr = r0 - 2 + rr;
        gr = gr < 0 ? -gr : (gr > HH - 1 ? 2 * (HH - 1) - gr : gr);
        const float4* base = (const float4*)(img + gr * WW) + c4;
        float4 r4 = base[0];
        float4 g4 = base[(HH * WW) / 4];
        float4 b4 = base[(2 * HH * WW) / 4];
        __half2 h01 = __floats2half2_rn(grayq(r4.x, g4.x, b4.x), grayq(r4.y, g4.y, b4.y));
        __half2 h23 = __floats2half2_rn(grayq(r4.z, g4.z, b4.z), grayq(r4.w, g4.w, b4.w));
        uint2 pk; pk.x = h2u(h01); pk.y = h2u(h23);
        *reinterpret_cast<uint2*>(&sg2[rr * 256 + 2 * c4]) = pk;
    }
    __syncthreads();

    // Stage 2: magnitude + direction class, fixed 6 trips with guard (34*128 = 4352)
#pragma unroll
    for (int k = 0; k < 6; k++) {
        int p = tid + k * FTHREADS;
        if (p < MAG_ROWS * 128) {
            int rr = p >> 7, c4 = p & 127;
            int gr = r0 - 1 + rr;
            __half2 m20 = __floats2half2_rn(0.0f, 0.0f);
            __half2 m21 = m20;
            if (gr >= 0 && gr < HH) {
                int sr = rr + 1;
                __half2 tL, tC0, tR, tC1, tR1;
                __half2 mL, mC0, mR, mC1, mR1;
                __half2 bL, bC0, bR, bC1, bR1;
                gquad(sg2 + (sr - 1) * 256, c4, tL, tC0, tR, tC1, tR1);
                gquad(sg2 +  sr      * 256, c4, mL, mC0, mR, mC1, mR1);
                gquad(sg2 + (sr + 1) * 256, c4, bL, bC0, bR, bC1, bR1);
                __half2 gx0, gy0, gx1, gy1;
                sobel2(tL, tC0, tR,  mL, mR,  bL, bC0, bR,  gx0, gy0);   // pair0
                sobel2(tR, tC1, tR1, mR, mR1, bR, bC1, bR1, gx1, gy1);   // pair1 (L1=R0)
                m20 = __hadd2(__habs2(gx0), __habs2(gy0));   // <= 2040, exact
                m21 = __hadd2(__habs2(gx1), __habs2(gy1));
                if (rr >= 1 && rr <= TILE_H) {
                    int cb = classify2(gx0, gy0) | (classify2(gx1, gy1) << 4);
                    sdc[(rr - 1) * 128 + c4] = (uint8_t)cb;
                }
            }
            uint2 pk; pk.x = h2u(m20); pk.y = h2u(m21);
            *reinterpret_cast<uint2*>(&sm2[rr * MAGP2 + 2 * c4 + 2]) = pk;
        }
    }
    {
        uint2 z2; z2.x = 0u; z2.y = 0u;
        for (int r = tid; r < MAG_ROWS; r += FTHREADS) {
            *reinterpret_cast<uint2*>(&sm2[r * MAGP2])       = z2;
            *reinterpret_cast<uint2*>(&sm2[r * MAGP2 + 258]) = z2;
        }
    }
    __syncthreads();

    // Stage 3: NMS + threshold + bitpack, fixed 6 trips with guard (32*128 = 4096)
    const int lane = tid & 31;
    const size_t obase = ((size_t)(im * BATCH + b)) * WORDS_PER_IMG;
    const __half2 h25 = __floats2half2_rn(25.0f, 25.0f);
    const __half2 h76 = __floats2half2_rn(76.0f, 76.0f);
#pragma unroll
    for (int k = 0; k < 6; k++) {
        int pt = tid + k * FTHREADS;
        if (pt < TILE_H * 128) {
            int rr = pt >> 7, c4 = pt & 127;       // rr uniform per warp

            __half2 tL, tC0, tR, tC1, tR1;
            __half2 mL, mC0, mR, mC1, mR1;
            __half2 bL, bC0, bR, bC1, bR1;
            mquad(sm2 +  rr      * MAGP2, c4, tL, tC0, tR, tC1, tR1);
            mquad(sm2 + (rr + 1) * MAGP2, c4, mL, mC0, mR, mC1, mR1);
            mquad(sm2 + (rr + 2) * MAGP2, c4, bL, bC0, bR, bC1, bR1);

            // pair0 (cols c, c+1)
            unsigned kh0 = __hgt2_mask(mC0, mL)  & __hge2_mask(mC0, mR);
            unsigned kv0 = __hgt2_mask(mC0, tC0) & __hge2_mask(mC0, bC0);
            unsigned k10 = __hgt2_mask(mC0, tL)  & __hge2_mask(mC0, bR);
            unsigned k20 = __hgt2_mask(mC0, tR)  & __hge2_mask(mC0, bL);
            unsigned wm0 = __hgt2_mask(mC0, h25);
            unsigned sm0 = __hgt2_mask(mC0, h76);
            // pair1 (cols c+2, c+3)
            unsigned kh1 = __hgt2_mask(mC1, mR)  & __hge2_mask(mC1, mR1);
            unsigned kv1 = __hgt2_mask(mC1, tC1) & __hge2_mask(mC1, bC1);
            unsigned k11 = __hgt2_mask(mC1, tR)  & __hge2_mask(mC1, bR1);
            unsigned k21 = __hgt2_mask(mC1, tR1) & __hge2_mask(mC1, bR);
            unsigned wm1 = __hgt2_mask(mC1, h25);
            unsigned sm1 = __hgt2_mask(mC1, h76);

            int cb = sdc[rr * 128 + c4];
            int c0 = cb & 3, c1 = (cb >> 2) & 3, c2_ = (cb >> 4) & 3, c3 = (cb >> 6) & 3;
            unsigned s0 = c0 == 0 ? kh0 : (c0 == 1 ? kv0 : (c0 == 2 ? k10 : k20));
            unsigned s1 = c1 == 0 ? kh0 : (c1 == 1 ? kv0 : (c1 == 2 ? k10 : k20));
            unsigned s2 = c2_ == 0 ? kh1 : (c2_ == 1 ? kv1 : (c2_ == 2 ? k11 : k21));
            unsigned s3 = c3 == 0 ? kh1 : (c3 == 1 ? kv1 : (c3 == 2 ? k11 : k21));
            bool wk0 =  (s0 & wm0)         & 1u;
            bool st0 =  (s0 & sm0)         & 1u;
            bool wk1 = ((s1 & wm0) >> 16)  & 1u;
            bool st1 = ((s1 & sm0) >> 16)  & 1u;
            bool wk2 =  (s2 & wm1)         & 1u;
            bool st2 =  (s2 & sm1)         & 1u;
            bool wk3 = ((s3 & wm1) >> 16)  & 1u;
            bool st3 = ((s3 & sm1) >> 16)  & 1u;

            unsigned bw0 = __ballot_sync(0xffffffffu, wk0);
            unsigned bw1 = __ballot_sync(0xffffffffu, wk1);
            unsigned bw2 = __ballot_sync(0xffffffffu, wk2);
            unsigned bw3 = __ballot_sync(0xffffffffu, wk3);
            unsigned bs0 = __ballot_sync(0xffffffffu, st0);
            unsigned bs1 = __ballot_sync(0xffffffffu, st1);
            unsigned bs2 = __ballot_sync(0xffffffffu, st2);
            unsigned bs3 = __ballot_sync(0xffffffffu, st3);

            if (lane < 8) {
                int m = lane & 3;
                bool is_st = lane >= 4;          // lanes 0-3 weak, 4-7 strong
                unsigned x0 = is_st ? bs0 : bw0;
                unsigned x1 = is_st ? bs1 : bw1;
                unsigned x2 = is_st ? bs2 : bw2;
                unsigned x3 = is_st ? bs3 : bw3;
                int sh = 8 * m;
                unsigned wordv = spread4(x0 >> sh) | (spread4(x1 >> sh) << 1)
                               | (spread4(x2 >> sh) << 2) | (spread4(x3 >> sh) << 3);
                uint32_t* dst = is_st ? (g_strong + obase) : (g_weak + obase);
                int wbase = (c4 & ~31) >> 3;           // warp's first word index
                dst[(size_t)(r0 + rr) * WPR + wbase + m] = wordv;
            }
        }
    }
}

// ---------------- hysteresis + fused diff ----------------------------------
// 1 CTA per (image,batch); im=0 publishes edges, im=1 diffs in-register.
// smem buffers pitch 20 words (80B): 16B-aligned, conflict-free for uint4 ops.
__global__ __launch_bounds__(512) void k_hyster(float* out, int n) {
    extern __shared__ uint32_t sbuf[];   // 2 buffers of [512][HPITCH]
    const int t = threadIdx.x;           // row index 0..511
    const int im = blockIdx.x >> 5, b = blockIdx.x & 31;
    const size_t base = ((size_t)(im * BATCH + b)) * WORDS_PER_IMG + (size_t)t * WPR;

    uint32_t w[WPR], s[WPR], c[WPR];
    {
        const uint4* pw = (const uint4*)(g_weak + base);
        const uint4* ps = (const uint4*)(g_strong + base);
#pragma unroll
        for (int q = 0; q < 4; q++) {
            uint4 a = pw[q];
            w[4*q+0]=a.x; w[4*q+1]=a.y; w[4*q+2]=a.z; w[4*q+3]=a.w;
            uint4 d = ps[q];
            s[4*q+0]=d.x; s[4*q+1]=d.y; s[4*q+2]=d.z; s[4*q+3]=d.w;
        }
    }
#pragma unroll
    for (int i = 0; i < WPR; i++) c[i] = s[i];

    uint32_t* b0 = sbuf;
    uint32_t* b1 = sbuf + HH * HPITCH;
    {
        uint4* p0 = (uint4*)(b0 + t * HPITCH);
#pragma unroll
        for (int q = 0; q < 4; q++)
            p0[q] = make_uint4(c[4*q+0], c[4*q+1], c[4*q+2], c[4*q+3]);
    }
    __syncthreads();

    const uint4 zero4 = make_uint4(0u, 0u, 0u, 0u);
    for (int it = 0; it < 64; ++it) {
        const uint32_t* rd = (it & 1) ? b1 : b0;
        uint32_t*       wr = (it & 1) ? b0 : b1;
        const uint4* pu = (const uint4*)(rd + (t - 1) * HPITCH);
        const uint4* pd = (const uint4*)(rd + (t + 1) * HPITCH);
        uint32_t vor[WPR];
#pragma unroll
        for (int q = 0; q < 4; q++) {
            uint4 u = (t > 0)      ? pu[q] : zero4;
            uint4 d = (t < HH - 1) ? pd[q] : zero4;
            vor[4*q+0] = u.x | d.x | c[4*q+0];
            vor[4*q+1] = u.y | d.y | c[4*q+1];
            vor[4*q+2] = u.z | d.z | c[4*q+2];
            vor[4*q+3] = u.w | d.w | c[4*q+3];
        }
        uint32_t ch = 0u;
        uint32_t outw[WPR];
#pragma unroll
        for (int i = 0; i < WPR; i++) {
            uint32_t lo = (i > 0)       ? vor[i - 1] : 0u;
            uint32_t hi = (i < WPR - 1) ? vor[i + 1] : 0u;
            uint32_t l = __funnelshift_l(lo, vor[i], 1);   // col-1 values
            uint32_t r = __funnelshift_r(vor[i], hi, 1);   // col+1 values
            uint32_t d3 = l | vor[i] | r;                  // 3x3 dilate done
            uint32_t nv = (d3 & w[i]) | s[i];
            ch |= nv ^ c[i];
            c[i] = nv;
            outw[i] = nv;
        }
        {
            uint4* po = (uint4*)(wr + t * HPITCH);
#pragma unroll
            for (int q = 0; q < 4; q++)
                po[q] = make_uint4(outw[4*q+0], outw[4*q+1], outw[4*q+2], outw[4*q+3]);
        }
        int any = __syncthreads_or((int)(ch != 0u));
        if (!any) break;  // fixed point => identical to reference while_loop
    }

    if (im == 0) {
        // publish edges + release flag
        uint4* pe = (uint4*)(g_edges + (size_t)b * WORDS_PER_IMG + (size_t)t * WPR);
#pragma unroll
        for (int q = 0; q < 4; q++)
            pe[q] = make_uint4(c[4*q+0], c[4*q+1], c[4*q+2], c[4*q+3]);
        __threadfence();
        __syncthreads();
        if (t == 0) atomicExch(&g_flag[b], 1u);
    } else {
        // acquire partner edges, then diff in-register
        if (t == 0) {
            while (atomicAdd(&g_flag[b], 0u) == 0u) __nanosleep(64);
            __threadfence();
        }
        __syncthreads();
        __threadfence();
        const uint4* pe = (const uint4*)(g_edges + (size_t)b * WORDS_PER_IMG + (size_t)t * WPR);
        int sum = 0;
#pragma unroll
        for (int q = 0; q < 4; q++) {
            uint4 e = pe[q];
            sum += __popc(c[4*q+0] ^ e.x) + __popc(c[4*q+1] ^ e.y)
                 + __popc(c[4*q+2] ^ e.z) + __popc(c[4*q+3] ^ e.w);
        }
#pragma unroll
        for (int o = 16; o > 0; o >>= 1) sum += __shfl_down_sync(0xffffffffu, sum, o);
        __syncthreads();                       // sbuf reuse safe
        int* ws = (int*)sbuf;
        if ((t & 31) == 0) ws[t >> 5] = sum;
        __syncthreads();
        if (t == 0) {
            int s2 = 0;
#pragma unroll
            for (int i = 0; i < 16; i++) s2 += ws[i];
            atomicAdd(&g_count, (unsigned)s2);
            __threadfence();
            unsigned ticket = atomicAdd(&g_done, 1u);
            if (ticket == BATCH - 1) {          // last diff block finalizes
                float v = sqrtf((float)atomicAdd(&g_count, 0u));
                for (int i = 0; i < n; i++) out[i] = v;
            }
        }
    }
}

// ---------------- launch ---------------------------------------------------
extern "C" void kernel_launch(void* const* d_in, const int* in_sizes, int n_in,
                              void* d_out, int out_size) {
    const float* A = (const float*)d_in[0];
    const float* B = (const float*)d_in[1];

    size_t smemF = (size_t)(GRAY_ROWS * 256 + MAG_ROWS * MAGP2) * sizeof(__half2)
                 + (size_t)TILE_H * 128;                                      // ~74.5KB
    size_t smemH = (size_t)2 * HH * HPITCH * sizeof(uint32_t);                // 81,920B

    cudaFuncSetAttribute(k_frontend, cudaFuncAttributeMaxDynamicSharedMemorySize, (int)smemF);
    cudaFuncSetAttribute(k_hyster,   cudaFuncAttributeMaxDynamicSharedMemorySize, (int)smemH);

    k_frontend<<<dim3(HH / TILE_H, BATCH, 2), FTHREADS, smemF>>>(A, B);
    k_hyster<<<2 * BATCH, 512, smemH>>>((float*)d_out, out_size);
}